// round 12
// baseline (speedup 1.0000x reference)
#include <cuda_runtime.h>
#include <cstdint>

// Problem dims (fixed by the dataset): B=4, S=2048, D=2048, H=8192
#define TOK 8192
#define DD  2048
#define HH  8192
#define NW  (HH*DD)
#define N4  (NW/4)            // 4194304 = 16384 * 256

// ---------------- device scratch (allocation-free rule) ----------------------
__device__ __align__(16) int8_t g_w1q[(size_t)NW];
__device__ __align__(16) int8_t g_w2q[(size_t)NW];
__device__ __align__(16) int8_t g_w3q[(size_t)NW];
__device__ __align__(16) int8_t g_xq1[(size_t)TOK * DD];
__device__ __align__(16) int8_t g_xq2[(size_t)TOK * DD];
__device__ __align__(16) int8_t g_hq [(size_t)TOK * HH];
__device__ __align__(16) float  g_y1[(size_t)TOK * HH];
__device__ __align__(16) float  g_y2[(size_t)TOK * HH];
__device__ float g_f1[TOK];
__device__ float g_f2[TOK];
__device__ float g_f3[TOK];
__device__ float g_partial[3][1024];
__device__ float g_wsum[3];

// ---------------- helpers -----------------------------------------------------
__device__ __forceinline__ float blk_sum(float v, float* sh) {
    int tid = threadIdx.x;
    sh[tid] = v; __syncthreads();
#pragma unroll
    for (int o = 128; o > 0; o >>= 1) { if (tid < o) sh[tid] += sh[tid + o]; __syncthreads(); }
    float r = sh[0]; __syncthreads();
    return r;
}
__device__ __forceinline__ float blk_max(float v, float* sh) {
    int tid = threadIdx.x;
    sh[tid] = v; __syncthreads();
#pragma unroll
    for (int o = 128; o > 0; o >>= 1) { if (tid < o) sh[tid] = fmaxf(sh[tid], sh[tid + o]); __syncthreads(); }
    float r = sh[0]; __syncthreads();
    return r;
}
__device__ __forceinline__ signed char quant1(float v, float sc) {
    float q = rintf(v * sc);
    q = fminf(fmaxf(q, -128.f), 127.f);
    return (signed char)(int)q;
}

// ---------------- 0) |w| reduction, all 3 matrices in one launch ---------------
__global__ void k_reduce_abs_all(const float4* __restrict__ w1,
                                 const float4* __restrict__ w2,
                                 const float4* __restrict__ w3) {
    __shared__ float sh[256];
    int slot = blockIdx.y;
    const float4* w4 = (slot == 0) ? w1 : (slot == 1) ? w2 : w3;
    int tid = threadIdx.x;
    float s = 0.f;
    for (int i = blockIdx.x * blockDim.x + tid; i < N4; i += gridDim.x * blockDim.x) {
        float4 v = w4[i];
        s += fabsf(v.x) + fabsf(v.y) + fabsf(v.z) + fabsf(v.w);
    }
    sh[tid] = s; __syncthreads();
#pragma unroll
    for (int o = 128; o > 0; o >>= 1) { if (tid < o) sh[tid] += sh[tid + o]; __syncthreads(); }
    if (tid == 0) g_partial[slot][blockIdx.x] = sh[0];
}

// ---------------- 1) finalize weight sums --------------------------------------
__global__ void k_finalize() {
    __shared__ float sh[256];
    int tid = threadIdx.x;
    for (int slot = 0; slot < 3; slot++) {
        float s = g_partial[slot][tid] + g_partial[slot][tid + 256]
                + g_partial[slot][tid + 512] + g_partial[slot][tid + 768];
        sh[tid] = s; __syncthreads();
#pragma unroll
        for (int o = 128; o > 0; o >>= 1) { if (tid < o) sh[tid] += sh[tid + o]; __syncthreads(); }
        if (tid == 0) g_wsum[slot] = sh[0];
        __syncthreads();
    }
}

// ---------------- 2) prep: ternarize weights + rmsnorm/act_quant of x ----------
// blocks [0, 49152): weight quant (slot = bid>>14, 256 float4 per block)
// blocks [49152, 57344): per-token activation quant
#define QW_BLOCKS (3 * 16384)
__global__ void k_prep(const float4* __restrict__ w1,
                       const float4* __restrict__ w2,
                       const float4* __restrict__ w3,
                       const float* __restrict__ x,
                       const float* __restrict__ g1v,
                       const float* __restrict__ g2v) {
    __shared__ float sh[256];
    int bid = blockIdx.x, tid = threadIdx.x;

    if (bid < QW_BLOCKS) {
        // ---- ternarize: round(tanh(z)) == (|z| >= atanh(0.5)) ----
        int slot = bid >> 14;
        int i = (bid & 16383) * 256 + tid;
        const float4* w4 = (slot == 0) ? w1 : (slot == 1) ? w2 : w3;
        float s   = g_wsum[slot] * (1.0f / (float)NW);
        float thr = 0.5493061443340549f * (s + 1e-8f);   // atanh(0.5) * (s+eps)
        char4* dst = (slot == 0) ? (char4*)g_w1q : (slot == 1) ? (char4*)g_w2q : (char4*)g_w3q;
        float4 v = w4[i];
        char4 q;
        q.x = (fabsf(v.x) >= thr) ? (v.x > 0.f ? 1 : -1) : 0;
        q.y = (fabsf(v.y) >= thr) ? (v.y > 0.f ? 1 : -1) : 0;
        q.z = (fabsf(v.z) >= thr) ? (v.z > 0.f ? 1 : -1) : 0;
        q.w = (fabsf(v.w) >= thr) ? (v.w > 0.f ? 1 : -1) : 0;
        dst[i] = q;
        return;
    }

    // ---- per-token rmsnorm + act_quant (both branches) ----
    int t = bid - QW_BLOCKS;
    const float4* xr = reinterpret_cast<const float4*>(x + (size_t)t * DD);
    float4 v0 = xr[2 * tid], v1 = xr[2 * tid + 1];
    float ss = v0.x * v0.x + v0.y * v0.y + v0.z * v0.z + v0.w * v0.w
             + v1.x * v1.x + v1.y * v1.y + v1.z * v1.z + v1.w * v1.w;
    float tot = blk_sum(ss, sh);
    float r = rsqrtf(tot * (1.0f / (float)DD) + 1e-8f);

    {
        const float4* gr = reinterpret_cast<const float4*>(g1v);
        float4 a0 = gr[2 * tid], a1 = gr[2 * tid + 1];
        float w0x = a0.x * v0.x * r, w0y = a0.y * v0.y * r, w0z = a0.z * v0.z * r, w0w = a0.w * v0.w * r;
        float w1x = a1.x * v1.x * r, w1y = a1.y * v1.y * r, w1z = a1.z * v1.z * r, w1w = a1.w * v1.w * r;
        float m = fmaxf(fmaxf(fmaxf(fabsf(w0x), fabsf(w0y)), fmaxf(fabsf(w0z), fabsf(w0w))),
                        fmaxf(fmaxf(fabsf(w1x), fabsf(w1y)), fmaxf(fabsf(w1z), fabsf(w1w))));
        m = blk_max(m, sh);
        float mc = fmaxf(m, 1e-4f);
        float sc = 127.0f / mc;
        char4 q0, q1;
        q0.x = quant1(w0x, sc); q0.y = quant1(w0y, sc); q0.z = quant1(w0z, sc); q0.w = quant1(w0w, sc);
        q1.x = quant1(w1x, sc); q1.y = quant1(w1y, sc); q1.z = quant1(w1z, sc); q1.w = quant1(w1w, sc);
        char4* outp = reinterpret_cast<char4*>(g_xq1 + (size_t)t * DD);
        outp[2 * tid] = q0; outp[2 * tid + 1] = q1;
        if (tid == 0) g_f1[t] = atanhf(g_wsum[0] * (1.0f / (float)NW)) * (mc * (1.0f / 127.0f));
    }
    {
        const float4* gr = reinterpret_cast<const float4*>(g2v);
        float4 a0 = gr[2 * tid], a1 = gr[2 * tid + 1];
        float w0x = a0.x * v0.x * r, w0y = a0.y * v0.y * r, w0z = a0.z * v0.z * r, w0w = a0.w * v0.w * r;
        float w1x = a1.x * v1.x * r, w1y = a1.y * v1.y * r, w1z = a1.z * v1.z * r, w1w = a1.w * v1.w * r;
        float m = fmaxf(fmaxf(fmaxf(fabsf(w0x), fabsf(w0y)), fmaxf(fabsf(w0z), fabsf(w0w))),
                        fmaxf(fmaxf(fabsf(w1x), fabsf(w1y)), fmaxf(fabsf(w1z), fabsf(w1w))));
        m = blk_max(m, sh);
        float mc = fmaxf(m, 1e-4f);
        float sc = 127.0f / mc;
        char4 q0, q1;
        q0.x = quant1(w0x, sc); q0.y = quant1(w0y, sc); q0.z = quant1(w0z, sc); q0.w = quant1(w0w, sc);
        q1.x = quant1(w1x, sc); q1.y = quant1(w1y, sc); q1.z = quant1(w1z, sc); q1.w = quant1(w1w, sc);
        char4* outp = reinterpret_cast<char4*>(g_xq2 + (size_t)t * DD);
        outp[2 * tid] = q0; outp[2 * tid + 1] = q1;
        if (tid == 0) g_f2[t] = atanhf(g_wsum[1] * (1.0f / (float)NW)) * (mc * (1.0f / 127.0f));
    }
}

// ---------------- 4) silu(y1)*y2 -> rmsnorm(g3) -> act_quant -> hq -------------
__global__ void k_combine(const float* __restrict__ g3v) {
    __shared__ float sh[256];
    int t = blockIdx.x, tid = threadIdx.x;
    const float4* y1r = reinterpret_cast<const float4*>(g_y1 + (size_t)t * HH);
    const float4* y2r = reinterpret_cast<const float4*>(g_y2 + (size_t)t * HH);
    float4 h[8];
    float ss = 0.f;
#pragma unroll
    for (int j = 0; j < 8; j++) {
        float4 a = y1r[tid + 256 * j];
        float4 b = y2r[tid + 256 * j];
        float4 hv;
        hv.x = a.x / (1.f + expf(-a.x)) * b.x;
        hv.y = a.y / (1.f + expf(-a.y)) * b.y;
        hv.z = a.z / (1.f + expf(-a.z)) * b.z;
        hv.w = a.w / (1.f + expf(-a.w)) * b.w;
        ss += hv.x * hv.x + hv.y * hv.y + hv.z * hv.z + hv.w * hv.w;
        h[j] = hv;
    }
    float tot = blk_sum(ss, sh);
    float r = rsqrtf(tot * (1.0f / (float)HH) + 1e-8f);
    const float4* gr = reinterpret_cast<const float4*>(g3v);
    float m = 0.f;
#pragma unroll
    for (int j = 0; j < 8; j++) {
        float4 g = gr[tid + 256 * j];
        m = fmaxf(m, fmaxf(fmaxf(fabsf(g.x * h[j].x * r), fabsf(g.y * h[j].y * r)),
                           fmaxf(fabsf(g.z * h[j].z * r), fabsf(g.w * h[j].w * r))));
    }
    m = blk_max(m, sh);
    float mc = fmaxf(m, 1e-4f);
    float sc = 127.0f / mc;
    char4* outp = reinterpret_cast<char4*>(g_hq + (size_t)t * HH);
#pragma unroll
    for (int j = 0; j < 8; j++) {
        float4 g = gr[tid + 256 * j];
        char4 q;
        q.x = quant1(g.x * h[j].x * r, sc);
        q.y = quant1(g.y * h[j].y * r, sc);
        q.z = quant1(g.z * h[j].z * r, sc);
        q.w = quant1(g.w * h[j].w * r, sc);
        outp[tid + 256 * j] = q;
    }
    if (tid == 0) g_f3[t] = atanhf(g_wsum[2] * (1.0f / (float)NW)) * (mc * (1.0f / 127.0f));
}

// ---------------- 3/5) s8 GEMM: mma.sync, 4-stage, conflict-free ---------------
// C[M,N] = (A[M,K] . B[N,K]^T) * frow[m];  layer = layer_base + blockIdx.z
#define BM 128
#define BN 128
#define BK 64
#define NSTAGE 4
#define STAGE_BYTES ((BM + BN) * BK)             // 16384
#define GEMM_SMEM (NSTAGE * STAGE_BYTES)         // 65536

// Conflict-free swizzle over the true 128B bank period.
__device__ __forceinline__ uint32_t swz(uint32_t row, uint32_t chunk) {
    uint32_t pos  = ((row & 1u) << 2) | chunk;
    uint32_t line = row >> 1;
    return line * 128u + ((pos ^ (line & 7u)) << 4);
}

__device__ __forceinline__ void ldsm4(uint32_t* r, uint32_t addr) {
    asm volatile("ldmatrix.sync.aligned.m8n8.x4.shared.b16 {%0,%1,%2,%3}, [%4];"
                 : "=r"(r[0]), "=r"(r[1]), "=r"(r[2]), "=r"(r[3]) : "r"(addr));
}
__device__ __forceinline__ void mma_s8(int* d, const uint32_t* a, uint32_t b0, uint32_t b1) {
    asm volatile("mma.sync.aligned.m16n8k32.row.col.s32.s8.s8.s32 "
                 "{%0,%1,%2,%3}, {%4,%5,%6,%7}, {%8,%9}, {%0,%1,%2,%3};"
                 : "+r"(d[0]), "+r"(d[1]), "+r"(d[2]), "+r"(d[3])
                 : "r"(a[0]), "r"(a[1]), "r"(a[2]), "r"(a[3]), "r"(b0), "r"(b1));
}
__device__ __forceinline__ void cp16(uint32_t dst, const void* src) {
    asm volatile("cp.async.cg.shared.global [%0], [%1], 16;" :: "r"(dst), "l"(src));
}

__global__ void __launch_bounds__(256, 2) k_gemm_s8(int layer_base, float* __restrict__ Cext,
                                                    int N, int K) {
    int layer = layer_base + blockIdx.z;
    const int8_t* __restrict__ A;
    const int8_t* __restrict__ B;
    float* __restrict__ C;
    const float* __restrict__ frow;
    if (layer == 0)      { A = g_xq1; B = g_w1q; C = g_y1;  frow = g_f1; }
    else if (layer == 1) { A = g_xq2; B = g_w2q; C = g_y2;  frow = g_f2; }
    else                 { A = g_hq;  B = g_w3q; C = Cext;  frow = g_f3; }

    extern __shared__ int8_t smem[];
    uint32_t sbase = (uint32_t)__cvta_generic_to_shared(smem);

    int tid = threadIdx.x;
    int bm = blockIdx.y * BM, bn = blockIdx.x * BN;
    int warp = tid >> 5, lane = tid & 31;
    int wm = (warp >> 2) * 64;       // 2 warp rows x 64
    int wn = (warp & 3) * 32;        // 4 warp cols x 32

    // ---- loader mapping: 1024 16B-chunks per stage, 4 per thread --------------
    const int8_t* sp[4];
    uint32_t doff[4];
#pragma unroll
    for (int i = 0; i < 4; i++) {
        int g = tid + 256 * i;
        int isB = (g >= 512);
        int h = isB ? g - 512 : g;
        int row = h >> 2, chunk = h & 3;
        doff[i] = swz((uint32_t)row, (uint32_t)chunk) + (isB ? (uint32_t)(BM * BK) : 0u);
        sp[i] = (isB ? B + (size_t)(bn + row) * K : A + (size_t)(bm + row) * K)
                + (size_t)chunk * 16;
    }
    auto load_stage = [&](int s) {
        uint32_t tb = sbase + (uint32_t)(s & (NSTAGE - 1)) * STAGE_BYTES;
        size_t ko = (size_t)s * BK;
#pragma unroll
        for (int i = 0; i < 4; i++) cp16(tb + doff[i], sp[i] + ko);
    };

    int acc[4][4][4];
#pragma unroll
    for (int a = 0; a < 4; a++)
#pragma unroll
        for (int b = 0; b < 4; b++)
#pragma unroll
            for (int c = 0; c < 4; c++) acc[a][b][c] = 0;

    int nst = K / BK;

    // prologue: fill 3 of 4 stages
#pragma unroll
    for (int s = 0; s < NSTAGE - 1; s++) {
        load_stage(s);
        asm volatile("cp.async.commit_group;" ::: "memory");
    }

    for (int s = 0; s < nst; s++) {
        asm volatile("cp.async.wait_group %0;" :: "n"(NSTAGE - 2) : "memory");
        __syncthreads();

        // constant group count: issue next stage (or empty group) every iter
        if (s + NSTAGE - 1 < nst) load_stage(s + NSTAGE - 1);
        asm volatile("cp.async.commit_group;" ::: "memory");

        uint32_t tb  = sbase + (uint32_t)(s & (NSTAGE - 1)) * STAGE_BYTES;
        uint32_t tbB = tb + BM * BK;

        // B fragments: 4 nf tiles, each ldsm4 covers the full BK=64
        uint32_t bf[4][4];
#pragma unroll
        for (int nf = 0; nf < 4; nf++) {
            uint32_t row = (uint32_t)(wn + nf * 8 + (lane & 7));
            uint32_t chunk = (uint32_t)(lane >> 3);
            ldsm4(bf[nf], tbB + swz(row, chunk));
        }

#pragma unroll
        for (int ks = 0; ks < 2; ks++) {
            uint32_t af[4][4];
#pragma unroll
            for (int mf = 0; mf < 4; mf++) {
                int mat = lane >> 3;
                uint32_t row = (uint32_t)(wm + mf * 16 + ((mat & 1) << 3) + (lane & 7));
                uint32_t chunk = (uint32_t)(ks * 2 + (mat >> 1));
                ldsm4(af[mf], tb + swz(row, chunk));
            }
#pragma unroll
            for (int mf = 0; mf < 4; mf++)
#pragma unroll
                for (int nf = 0; nf < 4; nf++)
                    mma_s8(acc[mf][nf], af[mf], bf[nf][2 * ks], bf[nf][2 * ks + 1]);
        }
        __syncthreads();
    }

    // ---- epilogue: scale by per-row factor, write fp32 ------------------------
#pragma unroll
    for (int mf = 0; mf < 4; mf++) {
        int r0 = bm + wm + mf * 16 + (lane >> 2);
        float f0 = frow[r0];
        float f1 = frow[r0 + 8];
#pragma unroll
        for (int nf = 0; nf < 4; nf++) {
            int c0 = bn + wn + nf * 8 + ((lane & 3) << 1);
            float2 v0, v1;
            v0.x = (float)acc[mf][nf][0] * f0;
            v0.y = (float)acc[mf][nf][1] * f0;
            v1.x = (float)acc[mf][nf][2] * f1;
            v1.y = (float)acc[mf][nf][3] * f1;
            *reinterpret_cast<float2*>(C + (size_t)r0 * N + c0)       = v0;
            *reinterpret_cast<float2*>(C + (size_t)(r0 + 8) * N + c0) = v1;
        }
    }
}

// ---------------- host entry ----------------------------------------------------
extern "C" void kernel_launch(void* const* d_in, const int* in_sizes, int n_in,
                              void* d_out, int out_size) {
    const float* x  = (const float*)d_in[0];
    const float* w1 = (const float*)d_in[1];
    const float* g1 = (const float*)d_in[2];
    const float* w2 = (const float*)d_in[3];
    const float* g2 = (const float*)d_in[4];
    const float* w3 = (const float*)d_in[5];
    const float* g3 = (const float*)d_in[6];
    float* out = (float*)d_out;

    static bool attr_set = false;
    if (!attr_set) {
        cudaFuncSetAttribute(k_gemm_s8, cudaFuncAttributeMaxDynamicSharedMemorySize, GEMM_SMEM);
        attr_set = true;
    }

    // 0) weight abs-mean partials (all 3 matrices)
    k_reduce_abs_all<<<dim3(1024, 3), 256>>>((const float4*)w1, (const float4*)w2,
                                             (const float4*)w3);
    // 1) finalize sums
    k_finalize<<<1, 256>>>();

    // 2) prep: ternarize weights + rmsnorm/act_quant of x (single launch)
    k_prep<<<QW_BLOCKS + TOK, 256>>>((const float4*)w1, (const float4*)w2,
                                     (const float4*)w3, x, g1, g2);

    // 3) y1 and y2 in one fused launch (layer = blockIdx.z); profiled at index 3
    k_gemm_s8<<<dim3(HH / BN, TOK / BM, 2), 256, GEMM_SMEM>>>(0, nullptr, HH, DD);

    // 4) h = silu(y1)*y2 -> rmsnorm(g3) -> int8
    k_combine<<<TOK, 256>>>(g3);

    // 5) out  (M=8192, N=2048, K=8192)
    k_gemm_s8<<<dim3(DD / BN, TOK / BM, 1), 256, GEMM_SMEM>>>(2, out, DD, HH);
}

// round 15
// speedup vs baseline: 1.1889x; 1.1889x over previous
#include <cuda_runtime.h>
#include <cstdint>

// Problem dims (fixed by the dataset): B=4, S=2048, D=2048, H=8192
#define TOK 8192
#define DD  2048
#define HH  8192
#define NW  (HH*DD)
#define N4  (NW/4)

// ---------------- device scratch (allocation-free rule) ----------------------
__device__ __align__(16) int8_t g_w1q[(size_t)NW];
__device__ __align__(16) int8_t g_w2q[(size_t)NW];
__device__ __align__(16) int8_t g_w3q[(size_t)NW];
__device__ __align__(16) int8_t g_xq1[(size_t)TOK * DD];
__device__ __align__(16) int8_t g_xq2[(size_t)TOK * DD];
__device__ __align__(16) int8_t g_hq [(size_t)TOK * HH];
__device__ __align__(16) float  g_y1[(size_t)TOK * HH];
__device__ __align__(16) float  g_y2[(size_t)TOK * HH];
__device__ float g_f1[TOK];
__device__ float g_f2[TOK];
__device__ float g_f3[TOK];
__device__ float g_partial[3][1024];
__device__ float g_wsum[3];

// ---------------- helpers -----------------------------------------------------
__device__ __forceinline__ float blk_sum(float v, float* sh) {
    int tid = threadIdx.x;
    sh[tid] = v; __syncthreads();
#pragma unroll
    for (int o = 128; o > 0; o >>= 1) { if (tid < o) sh[tid] += sh[tid + o]; __syncthreads(); }
    float r = sh[0]; __syncthreads();
    return r;
}
__device__ __forceinline__ float blk_max(float v, float* sh) {
    int tid = threadIdx.x;
    sh[tid] = v; __syncthreads();
#pragma unroll
    for (int o = 128; o > 0; o >>= 1) { if (tid < o) sh[tid] = fmaxf(sh[tid], sh[tid + o]); __syncthreads(); }
    float r = sh[0]; __syncthreads();
    return r;
}
__device__ __forceinline__ signed char quant1(float v, float sc) {
    float q = rintf(v * sc);
    q = fminf(fmaxf(q, -128.f), 127.f);
    return (signed char)(int)q;
}

// ---------------- 0) |w| reduction, all 3 matrices in one launch ---------------
__global__ void k_reduce_abs_all(const float4* __restrict__ w1,
                                 const float4* __restrict__ w2,
                                 const float4* __restrict__ w3) {
    __shared__ float sh[256];
    int slot = blockIdx.y;
    const float4* w4 = (slot == 0) ? w1 : (slot == 1) ? w2 : w3;
    int tid = threadIdx.x;
    float s = 0.f;
    for (int i = blockIdx.x * blockDim.x + tid; i < N4; i += gridDim.x * blockDim.x) {
        float4 v = w4[i];
        s += fabsf(v.x) + fabsf(v.y) + fabsf(v.z) + fabsf(v.w);
    }
    sh[tid] = s; __syncthreads();
#pragma unroll
    for (int o = 128; o > 0; o >>= 1) { if (tid < o) sh[tid] += sh[tid + o]; __syncthreads(); }
    if (tid == 0) g_partial[slot][blockIdx.x] = sh[0];
}

// ---------------- 1) finalize weight sums --------------------------------------
__global__ void k_finalize() {
    __shared__ float sh[256];
    int tid = threadIdx.x;
    for (int slot = 0; slot < 3; slot++) {
        float s = g_partial[slot][tid] + g_partial[slot][tid + 256]
                + g_partial[slot][tid + 512] + g_partial[slot][tid + 768];
        sh[tid] = s; __syncthreads();
#pragma unroll
        for (int o = 128; o > 0; o >>= 1) { if (tid < o) sh[tid] += sh[tid + o]; __syncthreads(); }
        if (tid == 0) g_wsum[slot] = sh[0];
        __syncthreads();
    }
}

// ---------------- 2) prep: ternarize weights + rmsnorm/act_quant of x ----------
#define QW_BLOCKS (3 * 16384)
__global__ void k_prep(const float4* __restrict__ w1,
                       const float4* __restrict__ w2,
                       const float4* __restrict__ w3,
                       const float* __restrict__ x,
                       const float* __restrict__ g1v,
                       const float* __restrict__ g2v) {
    __shared__ float sh[256];
    int bid = blockIdx.x, tid = threadIdx.x;

    if (bid < QW_BLOCKS) {
        // ternarize: round(tanh(z)) == (|z| >= atanh(0.5))
        int slot = bid >> 14;
        int i = (bid & 16383) * 256 + tid;
        const float4* w4 = (slot == 0) ? w1 : (slot == 1) ? w2 : w3;
        float s   = g_wsum[slot] * (1.0f / (float)NW);
        float thr = 0.5493061443340549f * (s + 1e-8f);
        char4* dst = (slot == 0) ? (char4*)g_w1q : (slot == 1) ? (char4*)g_w2q : (char4*)g_w3q;
        float4 v = w4[i];
        char4 q;
        q.x = (fabsf(v.x) >= thr) ? (v.x > 0.f ? 1 : -1) : 0;
        q.y = (fabsf(v.y) >= thr) ? (v.y > 0.f ? 1 : -1) : 0;
        q.z = (fabsf(v.z) >= thr) ? (v.z > 0.f ? 1 : -1) : 0;
        q.w = (fabsf(v.w) >= thr) ? (v.w > 0.f ? 1 : -1) : 0;
        dst[i] = q;
        return;
    }

    int t = bid - QW_BLOCKS;
    const float4* xr = reinterpret_cast<const float4*>(x + (size_t)t * DD);
    float4 v0 = xr[2 * tid], v1 = xr[2 * tid + 1];
    float ss = v0.x * v0.x + v0.y * v0.y + v0.z * v0.z + v0.w * v0.w
             + v1.x * v1.x + v1.y * v1.y + v1.z * v1.z + v1.w * v1.w;
    float tot = blk_sum(ss, sh);
    float r = rsqrtf(tot * (1.0f / (float)DD) + 1e-8f);

    {
        const float4* gr = reinterpret_cast<const float4*>(g1v);
        float4 a0 = gr[2 * tid], a1 = gr[2 * tid + 1];
        float w0x = a0.x * v0.x * r, w0y = a0.y * v0.y * r, w0z = a0.z * v0.z * r, w0w = a0.w * v0.w * r;
        float w1x = a1.x * v1.x * r, w1y = a1.y * v1.y * r, w1z = a1.z * v1.z * r, w1w = a1.w * v1.w * r;
        float m = fmaxf(fmaxf(fmaxf(fabsf(w0x), fabsf(w0y)), fmaxf(fabsf(w0z), fabsf(w0w))),
                        fmaxf(fmaxf(fabsf(w1x), fabsf(w1y)), fmaxf(fabsf(w1z), fabsf(w1w))));
        m = blk_max(m, sh);
        float mc = fmaxf(m, 1e-4f);
        float sc = 127.0f / mc;
        char4 q0, q1;
        q0.x = quant1(w0x, sc); q0.y = quant1(w0y, sc); q0.z = quant1(w0z, sc); q0.w = quant1(w0w, sc);
        q1.x = quant1(w1x, sc); q1.y = quant1(w1y, sc); q1.z = quant1(w1z, sc); q1.w = quant1(w1w, sc);
        char4* outp = reinterpret_cast<char4*>(g_xq1 + (size_t)t * DD);
        outp[2 * tid] = q0; outp[2 * tid + 1] = q1;
        if (tid == 0) g_f1[t] = atanhf(g_wsum[0] * (1.0f / (float)NW)) * (mc * (1.0f / 127.0f));
    }
    {
        const float4* gr = reinterpret_cast<const float4*>(g2v);
        float4 a0 = gr[2 * tid], a1 = gr[2 * tid + 1];
        float w0x = a0.x * v0.x * r, w0y = a0.y * v0.y * r, w0z = a0.z * v0.z * r, w0w = a0.w * v0.w * r;
        float w1x = a1.x * v1.x * r, w1y = a1.y * v1.y * r, w1z = a1.z * v1.z * r, w1w = a1.w * v1.w * r;
        float m = fmaxf(fmaxf(fmaxf(fabsf(w0x), fabsf(w0y)), fmaxf(fabsf(w0z), fabsf(w0w))),
                        fmaxf(fmaxf(fabsf(w1x), fabsf(w1y)), fmaxf(fabsf(w1z), fabsf(w1w))));
        m = blk_max(m, sh);
        float mc = fmaxf(m, 1e-4f);
        float sc = 127.0f / mc;
        char4 q0, q1;
        q0.x = quant1(w0x, sc); q0.y = quant1(w0y, sc); q0.z = quant1(w0z, sc); q0.w = quant1(w0w, sc);
        q1.x = quant1(w1x, sc); q1.y = quant1(w1y, sc); q1.z = quant1(w1z, sc); q1.w = quant1(w1w, sc);
        char4* outp = reinterpret_cast<char4*>(g_xq2 + (size_t)t * DD);
        outp[2 * tid] = q0; outp[2 * tid + 1] = q1;
        if (tid == 0) g_f2[t] = atanhf(g_wsum[1] * (1.0f / (float)NW)) * (mc * (1.0f / 127.0f));
    }
}

// ---------------- 4) silu(y1)*y2 -> rmsnorm(g3) -> act_quant -> hq -------------
__global__ void k_combine(const float* __restrict__ g3v) {
    __shared__ float sh[256];
    int t = blockIdx.x, tid = threadIdx.x;
    const float4* y1r = reinterpret_cast<const float4*>(g_y1 + (size_t)t * HH);
    const float4* y2r = reinterpret_cast<const float4*>(g_y2 + (size_t)t * HH);
    float4 h[8];
    float ss = 0.f;
#pragma unroll
    for (int j = 0; j < 8; j++) {
        float4 a = y1r[tid + 256 * j];
        float4 b = y2r[tid + 256 * j];
        float4 hv;
        hv.x = a.x / (1.f + expf(-a.x)) * b.x;
        hv.y = a.y / (1.f + expf(-a.y)) * b.y;
        hv.z = a.z / (1.f + expf(-a.z)) * b.z;
        hv.w = a.w / (1.f + expf(-a.w)) * b.w;
        ss += hv.x * hv.x + hv.y * hv.y + hv.z * hv.z + hv.w * hv.w;
        h[j] = hv;
    }
    float tot = blk_sum(ss, sh);
    float r = rsqrtf(tot * (1.0f / (float)HH) + 1e-8f);
    const float4* gr = reinterpret_cast<const float4*>(g3v);
    float m = 0.f;
#pragma unroll
    for (int j = 0; j < 8; j++) {
        float4 g = gr[tid + 256 * j];
        m = fmaxf(m, fmaxf(fmaxf(fabsf(g.x * h[j].x * r), fabsf(g.y * h[j].y * r)),
                           fmaxf(fabsf(g.z * h[j].z * r), fabsf(g.w * h[j].w * r))));
    }
    m = blk_max(m, sh);
    float mc = fmaxf(m, 1e-4f);
    float sc = 127.0f / mc;
    char4* outp = reinterpret_cast<char4*>(g_hq + (size_t)t * HH);
#pragma unroll
    for (int j = 0; j < 8; j++) {
        float4 g = gr[tid + 256 * j];
        char4 q;
        q.x = quant1(g.x * h[j].x * r, sc);
        q.y = quant1(g.y * h[j].y * r, sc);
        q.z = quant1(g.z * h[j].z * r, sc);
        q.w = quant1(g.w * h[j].w * r, sc);
        outp[tid + 256 * j] = q;
    }
    if (tid == 0) g_f3[t] = atanhf(g_wsum[2] * (1.0f / (float)NW)) * (mc * (1.0f / 127.0f));
}

// ---------------- 3/5) hybrid s8 GEMM: IMMA warps + DP4A warps -----------------
// C[M,N] = (A[M,K] . B[N,K]^T) * frow[m]
// Warps 0-7 : mma.sync on cols [0,128) of the CTA tile (tensor pipe)
// Warps 8-15: dp4a on cols [128,256)                  (fma/alu pipes)
#define BM  128
#define BNT 128
#define BND 128
#define BN  (BNT + BND)
#define BK  64
#define NSTAGE 4
#define REG_A  0
#define REG_BT (BM * BK)             // 8192
#define REG_BD (REG_BT + BNT * BK)   // 16384
#define STAGE_BYTES ((BM + BN) * BK) // 24576
#define GEMM_SMEM (NSTAGE * STAGE_BYTES)  // 98304

// Conflict-free swizzle over the true 128B bank period.
__device__ __forceinline__ uint32_t swz(uint32_t row, uint32_t chunk) {
    uint32_t pos  = ((row & 1u) << 2) | chunk;
    uint32_t line = row >> 1;
    return line * 128u + ((pos ^ (line & 7u)) << 4);
}

__device__ __forceinline__ void ldsm4(uint32_t* r, uint32_t addr) {
    asm volatile("ldmatrix.sync.aligned.m8n8.x4.shared.b16 {%0,%1,%2,%3}, [%4];"
                 : "=r"(r[0]), "=r"(r[1]), "=r"(r[2]), "=r"(r[3]) : "r"(addr));
}
__device__ __forceinline__ void mma_s8(int* d, const uint32_t* a, uint32_t b0, uint32_t b1) {
    asm volatile("mma.sync.aligned.m16n8k32.row.col.s32.s8.s8.s32 "
                 "{%0,%1,%2,%3}, {%4,%5,%6,%7}, {%8,%9}, {%0,%1,%2,%3};"
                 : "+r"(d[0]), "+r"(d[1]), "+r"(d[2]), "+r"(d[3])
                 : "r"(a[0]), "r"(a[1]), "r"(a[2]), "r"(a[3]), "r"(b0), "r"(b1));
}
__device__ __forceinline__ void cp16(uint32_t dst, const void* src) {
    asm volatile("cp.async.cg.shared.global [%0], [%1], 16;" :: "r"(dst), "l"(src));
}
__device__ __forceinline__ void lds128(int* r, uint32_t addr) {
    asm volatile("ld.shared.v4.b32 {%0,%1,%2,%3}, [%4];"
                 : "=r"(r[0]), "=r"(r[1]), "=r"(r[2]), "=r"(r[3]) : "r"(addr));
}

__global__ void __launch_bounds__(512, 1) k_gemm_hy(int layer_base, float* __restrict__ Cext,
                                                    int N, int K) {
    int layer = layer_base + blockIdx.z;
    const int8_t* __restrict__ A;
    const int8_t* __restrict__ B;
    float* __restrict__ C;
    const float* __restrict__ frow;
    if (layer == 0)      { A = g_xq1; B = g_w1q; C = g_y1;  frow = g_f1; }
    else if (layer == 1) { A = g_xq2; B = g_w2q; C = g_y2;  frow = g_f2; }
    else                 { A = g_hq;  B = g_w3q; C = Cext;  frow = g_f3; }

    extern __shared__ int8_t smem[];
    uint32_t sbase = (uint32_t)__cvta_generic_to_shared(smem);

    int tid = threadIdx.x;
    int bm = blockIdx.y * BM, bn = blockIdx.x * BN;
    int warp = tid >> 5, lane = tid & 31;
    int nst = K / BK;

    // ---- loader mapping: 1536 16B-chunks/stage, 3 per thread ------------------
    const int8_t* sp[3];
    uint32_t doff[3];
#pragma unroll
    for (int i = 0; i < 3; i++) {
        int g = tid + 512 * i;
        int reg = g >> 9;               // 0=A, 1=B_t, 2=B_d
        int idx = g & 511;
        int row = idx >> 2, chunk = idx & 3;
        doff[i] = (uint32_t)reg * 8192u + swz((uint32_t)row, (uint32_t)chunk);
        const int8_t* base = (reg == 0) ? A + (size_t)(bm + row) * K
                           : (reg == 1) ? B + (size_t)(bn + row) * K
                                        : B + (size_t)(bn + BNT + row) * K;
        sp[i] = base + (size_t)chunk * 16;
    }
    auto load_stage = [&](int s) {
        uint32_t tb = sbase + (uint32_t)(s & (NSTAGE - 1)) * STAGE_BYTES;
        size_t ko = (size_t)s * BK;
#pragma unroll
        for (int i = 0; i < 3; i++) cp16(tb + doff[i], sp[i] + ko);
    };

    // prologue: fill 3 of 4 stages
#pragma unroll
    for (int s = 0; s < NSTAGE - 1; s++) {
        load_stage(s);
        asm volatile("cp.async.commit_group;" ::: "memory");
    }

    if (warp < 8) {
        // ================= IMMA half: cols [0,128) =============================
        int wm = (warp >> 2) * 64;
        int wn = (warp & 3) * 32;
        int acc[4][4][4];
#pragma unroll
        for (int a = 0; a < 4; a++)
#pragma unroll
            for (int b = 0; b < 4; b++)
#pragma unroll
                for (int c = 0; c < 4; c++) acc[a][b][c] = 0;

        for (int s = 0; s < nst; s++) {
            asm volatile("cp.async.wait_group %0;" :: "n"(NSTAGE - 2) : "memory");
            __syncthreads();
            if (s + NSTAGE - 1 < nst) load_stage(s + NSTAGE - 1);
            asm volatile("cp.async.commit_group;" ::: "memory");

            uint32_t tb  = sbase + (uint32_t)(s & (NSTAGE - 1)) * STAGE_BYTES;
            uint32_t tbB = tb + REG_BT;

            uint32_t bf[4][4];
#pragma unroll
            for (int nf = 0; nf < 4; nf++) {
                uint32_t row = (uint32_t)(wn + nf * 8 + (lane & 7));
                uint32_t chunk = (uint32_t)(lane >> 3);
                ldsm4(bf[nf], tbB + swz(row, chunk));
            }
#pragma unroll
            for (int ks = 0; ks < 2; ks++) {
                uint32_t af[4][4];
#pragma unroll
                for (int mf = 0; mf < 4; mf++) {
                    int mat = lane >> 3;
                    uint32_t row = (uint32_t)(wm + mf * 16 + ((mat & 1) << 3) + (lane & 7));
                    uint32_t chunk = (uint32_t)(ks * 2 + (mat >> 1));
                    ldsm4(af[mf], tb + swz(row, chunk));
                }
#pragma unroll
                for (int mf = 0; mf < 4; mf++)
#pragma unroll
                    for (int nf = 0; nf < 4; nf++)
                        mma_s8(acc[mf][nf], af[mf], bf[nf][2 * ks], bf[nf][2 * ks + 1]);
            }
            __syncthreads();
        }

        // epilogue (mma half)
#pragma unroll
        for (int mf = 0; mf < 4; mf++) {
            int r0 = bm + wm + mf * 16 + (lane >> 2);
            float f0 = frow[r0];
            float f1 = frow[r0 + 8];
#pragma unroll
            for (int nf = 0; nf < 4; nf++) {
                int c0 = bn + wn + nf * 8 + ((lane & 3) << 1);
                float2 v0, v1;
                v0.x = (float)acc[mf][nf][0] * f0;
                v0.y = (float)acc[mf][nf][1] * f0;
                v1.x = (float)acc[mf][nf][2] * f1;
                v1.y = (float)acc[mf][nf][3] * f1;
                *reinterpret_cast<float2*>(C + (size_t)r0 * N + c0)       = v0;
                *reinterpret_cast<float2*>(C + (size_t)(r0 + 8) * N + c0) = v1;
            }
        }
    } else {
        // ================= DP4A half: cols [128,256) ===========================
        int widd = warp - 8;
        int wm_d = (widd >> 2) * 64;     // row block: 64 rows
        int wn_d = (widd & 3) * 32;      // col block: 32 cols
        int rb = wm_d + (lane >> 2);     // thread rows: rb + 8*i (i<8)
        int cb = wn_d + (lane & 3);      // thread cols: cb + 4*j (j<8)

        int accd[8][8];
#pragma unroll
        for (int i = 0; i < 8; i++)
#pragma unroll
            for (int j = 0; j < 8; j++) accd[i][j] = 0;

        for (int s = 0; s < nst; s++) {
            asm volatile("cp.async.wait_group %0;" :: "n"(NSTAGE - 2) : "memory");
            __syncthreads();
            if (s + NSTAGE - 1 < nst) load_stage(s + NSTAGE - 1);
            asm volatile("cp.async.commit_group;" ::: "memory");

            uint32_t tb  = sbase + (uint32_t)(s & (NSTAGE - 1)) * STAGE_BYTES;
            uint32_t tbD = tb + REG_BD;

#pragma unroll
            for (int kb = 0; kb < 4; kb++) {
                int av[8][4];
#pragma unroll
                for (int i = 0; i < 8; i++)
                    lds128(av[i], tb + swz((uint32_t)(rb + 8 * i), (uint32_t)kb));
#pragma unroll
                for (int j = 0; j < 8; j++) {
                    int bv[4];
                    lds128(bv, tbD + swz((uint32_t)(cb + 4 * j), (uint32_t)kb));
#pragma unroll
                    for (int i = 0; i < 8; i++) {
                        accd[i][j] = __dp4a(av[i][0], bv[0], accd[i][j]);
                        accd[i][j] = __dp4a(av[i][1], bv[1], accd[i][j]);
                        accd[i][j] = __dp4a(av[i][2], bv[2], accd[i][j]);
                        accd[i][j] = __dp4a(av[i][3], bv[3], accd[i][j]);
                    }
                }
            }
            __syncthreads();
        }

        // epilogue (dp4a half)
#pragma unroll
        for (int i = 0; i < 8; i++) {
            int r = bm + rb + 8 * i;
            float f = frow[r];
            float* crow = C + (size_t)r * N + bn + BNT + cb;
#pragma unroll
            for (int j = 0; j < 8; j++)
                crow[4 * j] = (float)accd[i][j] * f;
        }
    }
}

// ---------------- host entry ----------------------------------------------------
extern "C" void kernel_launch(void* const* d_in, const int* in_sizes, int n_in,
                              void* d_out, int out_size) {
    const float* x  = (const float*)d_in[0];
    const float* w1 = (const float*)d_in[1];
    const float* g1 = (const float*)d_in[2];
    const float* w2 = (const float*)d_in[3];
    const float* g2 = (const float*)d_in[4];
    const float* w3 = (const float*)d_in[5];
    const float* g3 = (const float*)d_in[6];
    float* out = (float*)d_out;

    static bool attr_set = false;
    if (!attr_set) {
        cudaFuncSetAttribute(k_gemm_hy, cudaFuncAttributeMaxDynamicSharedMemorySize, GEMM_SMEM);
        attr_set = true;
    }

    // 0) weight abs-mean partials
    k_reduce_abs_all<<<dim3(1024, 3), 256>>>((const float4*)w1, (const float4*)w2,
                                             (const float4*)w3);
    // 1) finalize sums
    k_finalize<<<1, 256>>>();

    // 2) prep: ternarize weights + rmsnorm/act_quant of x
    k_prep<<<QW_BLOCKS + TOK, 256>>>((const float4*)w1, (const float4*)w2,
                                     (const float4*)w3, x, g1, g2);

    // 3) y1 and y2 fused (layer = blockIdx.z); lands at profile index 3
    k_gemm_hy<<<dim3(HH / BN, TOK / BM, 2), 512, GEMM_SMEM>>>(0, nullptr, HH, DD);

    // 4) h = silu(y1)*y2 -> rmsnorm(g3) -> int8
    k_combine<<<TOK, 256>>>(g3);

    // 5) out  (M=8192, N=2048, K=8192)
    k_gemm_hy<<<dim3(DD / BN, TOK / BM, 1), 512, GEMM_SMEM>>>(2, out, DD, HH);
}

// round 16
// speedup vs baseline: 1.2284x; 1.0332x over previous
#include <cuda_runtime.h>
#include <cstdint>

// Problem dims (fixed by the dataset): B=4, S=2048, D=2048, H=8192
#define TOK 8192
#define DD  2048
#define HH  8192
#define NW  (HH*DD)
#define N4  (NW/4)

// ---------------- device scratch (allocation-free rule) ----------------------
__device__ __align__(16) int8_t g_w1q[(size_t)NW];
__device__ __align__(16) int8_t g_w2q[(size_t)NW];
__device__ __align__(16) int8_t g_w3q[(size_t)NW];
__device__ __align__(16) int8_t g_xq1[(size_t)TOK * DD];
__device__ __align__(16) int8_t g_xq2[(size_t)TOK * DD];
__device__ __align__(16) int8_t g_hq [(size_t)TOK * HH];
__device__ __align__(16) float  g_y1[(size_t)TOK * HH];
__device__ __align__(16) float  g_y2[(size_t)TOK * HH];
__device__ float g_f1[TOK];
__device__ float g_f2[TOK];
__device__ float g_f3[TOK];
__device__ float g_partial[3][1024];
__device__ float g_wsum[3];

// ---------------- helpers -----------------------------------------------------
__device__ __forceinline__ float blk_sum(float v, float* sh) {
    int tid = threadIdx.x;
    sh[tid] = v; __syncthreads();
#pragma unroll
    for (int o = 128; o > 0; o >>= 1) { if (tid < o) sh[tid] += sh[tid + o]; __syncthreads(); }
    float r = sh[0]; __syncthreads();
    return r;
}
__device__ __forceinline__ float blk_max(float v, float* sh) {
    int tid = threadIdx.x;
    sh[tid] = v; __syncthreads();
#pragma unroll
    for (int o = 128; o > 0; o >>= 1) { if (tid < o) sh[tid] = fmaxf(sh[tid], sh[tid + o]); __syncthreads(); }
    float r = sh[0]; __syncthreads();
    return r;
}
__device__ __forceinline__ signed char quant1(float v, float sc) {
    float q = rintf(v * sc);
    q = fminf(fmaxf(q, -128.f), 127.f);
    return (signed char)(int)q;
}

// ---------------- 0) |w| reduction, all 3 matrices in one launch ---------------
__global__ void k_reduce_abs_all(const float4* __restrict__ w1,
                                 const float4* __restrict__ w2,
                                 const float4* __restrict__ w3) {
    __shared__ float sh[256];
    int slot = blockIdx.y;
    const float4* w4 = (slot == 0) ? w1 : (slot == 1) ? w2 : w3;
    int tid = threadIdx.x;
    float s = 0.f;
    for (int i = blockIdx.x * blockDim.x + tid; i < N4; i += gridDim.x * blockDim.x) {
        float4 v = w4[i];
        s += fabsf(v.x) + fabsf(v.y) + fabsf(v.z) + fabsf(v.w);
    }
    sh[tid] = s; __syncthreads();
#pragma unroll
    for (int o = 128; o > 0; o >>= 1) { if (tid < o) sh[tid] += sh[tid + o]; __syncthreads(); }
    if (tid == 0) g_partial[slot][blockIdx.x] = sh[0];
}

// ---------------- 1) finalize weight sums --------------------------------------
__global__ void k_finalize() {
    __shared__ float sh[256];
    int tid = threadIdx.x;
    for (int slot = 0; slot < 3; slot++) {
        float s = g_partial[slot][tid] + g_partial[slot][tid + 256]
                + g_partial[slot][tid + 512] + g_partial[slot][tid + 768];
        sh[tid] = s; __syncthreads();
#pragma unroll
        for (int o = 128; o > 0; o >>= 1) { if (tid < o) sh[tid] += sh[tid + o]; __syncthreads(); }
        if (tid == 0) g_wsum[slot] = sh[0];
        __syncthreads();
    }
}

// ---------------- 2) prep: ternarize weights + rmsnorm/act_quant of x ----------
#define QW_BLOCKS (3 * 16384)
__global__ void k_prep(const float4* __restrict__ w1,
                       const float4* __restrict__ w2,
                       const float4* __restrict__ w3,
                       const float* __restrict__ x,
                       const float* __restrict__ g1v,
                       const float* __restrict__ g2v) {
    __shared__ float sh[256];
    int bid = blockIdx.x, tid = threadIdx.x;

    if (bid < QW_BLOCKS) {
        // ternarize: round(tanh(z)) == (|z| >= atanh(0.5))
        int slot = bid >> 14;
        int i = (bid & 16383) * 256 + tid;
        const float4* w4 = (slot == 0) ? w1 : (slot == 1) ? w2 : w3;
        float s   = g_wsum[slot] * (1.0f / (float)NW);
        float thr = 0.5493061443340549f * (s + 1e-8f);
        char4* dst = (slot == 0) ? (char4*)g_w1q : (slot == 1) ? (char4*)g_w2q : (char4*)g_w3q;
        float4 v = w4[i];
        char4 q;
        q.x = (fabsf(v.x) >= thr) ? (v.x > 0.f ? 1 : -1) : 0;
        q.y = (fabsf(v.y) >= thr) ? (v.y > 0.f ? 1 : -1) : 0;
        q.z = (fabsf(v.z) >= thr) ? (v.z > 0.f ? 1 : -1) : 0;
        q.w = (fabsf(v.w) >= thr) ? (v.w > 0.f ? 1 : -1) : 0;
        dst[i] = q;
        return;
    }

    int t = bid - QW_BLOCKS;
    const float4* xr = reinterpret_cast<const float4*>(x + (size_t)t * DD);
    float4 v0 = xr[2 * tid], v1 = xr[2 * tid + 1];
    float ss = v0.x * v0.x + v0.y * v0.y + v0.z * v0.z + v0.w * v0.w
             + v1.x * v1.x + v1.y * v1.y + v1.z * v1.z + v1.w * v1.w;
    float tot = blk_sum(ss, sh);
    float r = rsqrtf(tot * (1.0f / (float)DD) + 1e-8f);

    {
        const float4* gr = reinterpret_cast<const float4*>(g1v);
        float4 a0 = gr[2 * tid], a1 = gr[2 * tid + 1];
        float w0x = a0.x * v0.x * r, w0y = a0.y * v0.y * r, w0z = a0.z * v0.z * r, w0w = a0.w * v0.w * r;
        float w1x = a1.x * v1.x * r, w1y = a1.y * v1.y * r, w1z = a1.z * v1.z * r, w1w = a1.w * v1.w * r;
        float m = fmaxf(fmaxf(fmaxf(fabsf(w0x), fabsf(w0y)), fmaxf(fabsf(w0z), fabsf(w0w))),
                        fmaxf(fmaxf(fabsf(w1x), fabsf(w1y)), fmaxf(fabsf(w1z), fabsf(w1w))));
        m = blk_max(m, sh);
        float mc = fmaxf(m, 1e-4f);
        float sc = 127.0f / mc;
        char4 q0, q1;
        q0.x = quant1(w0x, sc); q0.y = quant1(w0y, sc); q0.z = quant1(w0z, sc); q0.w = quant1(w0w, sc);
        q1.x = quant1(w1x, sc); q1.y = quant1(w1y, sc); q1.z = quant1(w1z, sc); q1.w = quant1(w1w, sc);
        char4* outp = reinterpret_cast<char4*>(g_xq1 + (size_t)t * DD);
        outp[2 * tid] = q0; outp[2 * tid + 1] = q1;
        if (tid == 0) g_f1[t] = atanhf(g_wsum[0] * (1.0f / (float)NW)) * (mc * (1.0f / 127.0f));
    }
    {
        const float4* gr = reinterpret_cast<const float4*>(g2v);
        float4 a0 = gr[2 * tid], a1 = gr[2 * tid + 1];
        float w0x = a0.x * v0.x * r, w0y = a0.y * v0.y * r, w0z = a0.z * v0.z * r, w0w = a0.w * v0.w * r;
        float w1x = a1.x * v1.x * r, w1y = a1.y * v1.y * r, w1z = a1.z * v1.z * r, w1w = a1.w * v1.w * r;
        float m = fmaxf(fmaxf(fmaxf(fabsf(w0x), fabsf(w0y)), fmaxf(fabsf(w0z), fabsf(w0w))),
                        fmaxf(fmaxf(fabsf(w1x), fabsf(w1y)), fmaxf(fabsf(w1z), fabsf(w1w))));
        m = blk_max(m, sh);
        float mc = fmaxf(m, 1e-4f);
        float sc = 127.0f / mc;
        char4 q0, q1;
        q0.x = quant1(w0x, sc); q0.y = quant1(w0y, sc); q0.z = quant1(w0z, sc); q0.w = quant1(w0w, sc);
        q1.x = quant1(w1x, sc); q1.y = quant1(w1y, sc); q1.z = quant1(w1z, sc); q1.w = quant1(w1w, sc);
        char4* outp = reinterpret_cast<char4*>(g_xq2 + (size_t)t * DD);
        outp[2 * tid] = q0; outp[2 * tid + 1] = q1;
        if (tid == 0) g_f2[t] = atanhf(g_wsum[1] * (1.0f / (float)NW)) * (mc * (1.0f / 127.0f));
    }
}

// ---------------- 4) silu(y1)*y2 -> rmsnorm(g3) -> act_quant -> hq -------------
__global__ void k_combine(const float* __restrict__ g3v) {
    __shared__ float sh[256];
    int t = blockIdx.x, tid = threadIdx.x;
    const float4* y1r = reinterpret_cast<const float4*>(g_y1 + (size_t)t * HH);
    const float4* y2r = reinterpret_cast<const float4*>(g_y2 + (size_t)t * HH);
    float4 h[8];
    float ss = 0.f;
#pragma unroll
    for (int j = 0; j < 8; j++) {
        float4 a = y1r[tid + 256 * j];
        float4 b = y2r[tid + 256 * j];
        float4 hv;
        hv.x = a.x / (1.f + expf(-a.x)) * b.x;
        hv.y = a.y / (1.f + expf(-a.y)) * b.y;
        hv.z = a.z / (1.f + expf(-a.z)) * b.z;
        hv.w = a.w / (1.f + expf(-a.w)) * b.w;
        ss += hv.x * hv.x + hv.y * hv.y + hv.z * hv.z + hv.w * hv.w;
        h[j] = hv;
    }
    float tot = blk_sum(ss, sh);
    float r = rsqrtf(tot * (1.0f / (float)HH) + 1e-8f);
    const float4* gr = reinterpret_cast<const float4*>(g3v);
    float m = 0.f;
#pragma unroll
    for (int j = 0; j < 8; j++) {
        float4 g = gr[tid + 256 * j];
        m = fmaxf(m, fmaxf(fmaxf(fabsf(g.x * h[j].x * r), fabsf(g.y * h[j].y * r)),
                           fmaxf(fabsf(g.z * h[j].z * r), fabsf(g.w * h[j].w * r))));
    }
    m = blk_max(m, sh);
    float mc = fmaxf(m, 1e-4f);
    float sc = 127.0f / mc;
    char4* outp = reinterpret_cast<char4*>(g_hq + (size_t)t * HH);
#pragma unroll
    for (int j = 0; j < 8; j++) {
        float4 g = gr[tid + 256 * j];
        char4 q;
        q.x = quant1(g.x * h[j].x * r, sc);
        q.y = quant1(g.y * h[j].y * r, sc);
        q.z = quant1(g.z * h[j].z * r, sc);
        q.w = quant1(g.w * h[j].w * r, sc);
        outp[tid + 256 * j] = q;
    }
    if (tid == 0) g_f3[t] = atanhf(g_wsum[2] * (1.0f / (float)NW)) * (mc * (1.0f / 127.0f));
}

// ---------------- 3/5) hybrid s8 GEMM: IMMA warps + DP4A warps -----------------
// C[M,N] = (A[M,K] . B[N,K]^T) * frow[m]
// Warps 0-7 : mma.sync on cols [0,160)   of the CTA tile (tensor pipe)
// Warps 8-15: dp4a     on cols [160,256)                 (fma/alu pipes)
#define BM  128
#define BNT 160
#define BND 96
#define BN  (BNT + BND)
#define BK  64
#define NSTAGE 4
#define REG_A_OFF  0
#define REG_BT_OFF (BM * BK)                 // 8192
#define REG_BD_OFF (REG_BT_OFF + BNT * BK)   // 18432
#define STAGE_BYTES ((BM + BN) * BK)         // 24576
#define GEMM_SMEM (NSTAGE * STAGE_BYTES)     // 98304
#define A_CHUNKS  (BM * 4)                   // 512
#define BT_CHUNKS (BNT * 4)                  // 640

// Conflict-free swizzle over the true 128B bank period.
__device__ __forceinline__ uint32_t swz(uint32_t row, uint32_t chunk) {
    uint32_t pos  = ((row & 1u) << 2) | chunk;
    uint32_t line = row >> 1;
    return line * 128u + ((pos ^ (line & 7u)) << 4);
}

__device__ __forceinline__ void ldsm4(uint32_t* r, uint32_t addr) {
    asm volatile("ldmatrix.sync.aligned.m8n8.x4.shared.b16 {%0,%1,%2,%3}, [%4];"
                 : "=r"(r[0]), "=r"(r[1]), "=r"(r[2]), "=r"(r[3]) : "r"(addr));
}
__device__ __forceinline__ void mma_s8(int* d, const uint32_t* a, uint32_t b0, uint32_t b1) {
    asm volatile("mma.sync.aligned.m16n8k32.row.col.s32.s8.s8.s32 "
                 "{%0,%1,%2,%3}, {%4,%5,%6,%7}, {%8,%9}, {%0,%1,%2,%3};"
                 : "+r"(d[0]), "+r"(d[1]), "+r"(d[2]), "+r"(d[3])
                 : "r"(a[0]), "r"(a[1]), "r"(a[2]), "r"(a[3]), "r"(b0), "r"(b1));
}
__device__ __forceinline__ void cp16(uint32_t dst, const void* src) {
    asm volatile("cp.async.cg.shared.global [%0], [%1], 16;" :: "r"(dst), "l"(src));
}
__device__ __forceinline__ void lds128(int* r, uint32_t addr) {
    asm volatile("ld.shared.v4.b32 {%0,%1,%2,%3}, [%4];"
                 : "=r"(r[0]), "=r"(r[1]), "=r"(r[2]), "=r"(r[3]) : "r"(addr));
}

__global__ void __launch_bounds__(512, 1) k_gemm_hy(int layer_base, float* __restrict__ Cext,
                                                    int N, int K) {
    int layer = layer_base + blockIdx.z;
    const int8_t* __restrict__ A;
    const int8_t* __restrict__ B;
    float* __restrict__ C;
    const float* __restrict__ frow;
    if (layer == 0)      { A = g_xq1; B = g_w1q; C = g_y1;  frow = g_f1; }
    else if (layer == 1) { A = g_xq2; B = g_w2q; C = g_y2;  frow = g_f2; }
    else                 { A = g_hq;  B = g_w3q; C = Cext;  frow = g_f3; }

    extern __shared__ int8_t smem[];
    uint32_t sbase = (uint32_t)__cvta_generic_to_shared(smem);

    int tid = threadIdx.x;
    int bm = blockIdx.y * BM, bn = blockIdx.x * BN;
    int warp = tid >> 5, lane = tid & 31;
    int nst = K / BK;

    // ---- loader mapping: 1536 16B-chunks/stage, 3 per thread ------------------
    // regions: A [0,512) -> smem 0; B_t [512,1152) -> 8192; B_d [1152,1536) -> 18432
    const int8_t* sp[3];
    uint32_t doff[3];
#pragma unroll
    for (int i = 0; i < 3; i++) {
        int g = tid + 512 * i;
        int idx, row, chunk;
        const int8_t* base;
        uint32_t roff;
        if (g < A_CHUNKS) {
            idx = g;               roff = REG_A_OFF;
            row = idx >> 2;        base = A + (size_t)(bm + row) * K;
        } else if (g < A_CHUNKS + BT_CHUNKS) {
            idx = g - A_CHUNKS;    roff = REG_BT_OFF;
            row = idx >> 2;        base = B + (size_t)(bn + row) * K;
        } else {
            idx = g - A_CHUNKS - BT_CHUNKS; roff = REG_BD_OFF;
            row = idx >> 2;        base = B + (size_t)(bn + BNT + row) * K;
        }
        chunk = idx & 3;
        doff[i] = roff + swz((uint32_t)row, (uint32_t)chunk);
        sp[i] = base + (size_t)chunk * 16;
    }
    auto load_stage = [&](int s) {
        uint32_t tb = sbase + (uint32_t)(s & (NSTAGE - 1)) * STAGE_BYTES;
        size_t ko = (size_t)s * BK;
#pragma unroll
        for (int i = 0; i < 3; i++) cp16(tb + doff[i], sp[i] + ko);
    };

    // prologue: fill 3 of 4 stages
#pragma unroll
    for (int s = 0; s < NSTAGE - 1; s++) {
        load_stage(s);
        asm volatile("cp.async.commit_group;" ::: "memory");
    }

    if (warp < 8) {
        // ================= IMMA half: cols [0,160), warp tile 64x40 ============
        int wm = (warp >> 2) * 64;
        int wn = (warp & 3) * 40;
        int acc[4][5][4];
#pragma unroll
        for (int a = 0; a < 4; a++)
#pragma unroll
            for (int b = 0; b < 5; b++)
#pragma unroll
                for (int c = 0; c < 4; c++) acc[a][b][c] = 0;

        for (int s = 0; s < nst; s++) {
            asm volatile("cp.async.wait_group %0;" :: "n"(NSTAGE - 2) : "memory");
            __syncthreads();
            if (s + NSTAGE - 1 < nst) load_stage(s + NSTAGE - 1);
            asm volatile("cp.async.commit_group;" ::: "memory");

            uint32_t tb  = sbase + (uint32_t)(s & (NSTAGE - 1)) * STAGE_BYTES;
            uint32_t tbB = tb + REG_BT_OFF;

            uint32_t bf[5][4];
#pragma unroll
            for (int nf = 0; nf < 5; nf++) {
                uint32_t row = (uint32_t)(wn + nf * 8 + (lane & 7));
                uint32_t chunk = (uint32_t)(lane >> 3);
                ldsm4(bf[nf], tbB + swz(row, chunk));
            }
#pragma unroll
            for (int ks = 0; ks < 2; ks++) {
                uint32_t af[4][4];
#pragma unroll
                for (int mf = 0; mf < 4; mf++) {
                    int mat = lane >> 3;
                    uint32_t row = (uint32_t)(wm + mf * 16 + ((mat & 1) << 3) + (lane & 7));
                    uint32_t chunk = (uint32_t)(ks * 2 + (mat >> 1));
                    ldsm4(af[mf], tb + swz(row, chunk));
                }
#pragma unroll
                for (int mf = 0; mf < 4; mf++)
#pragma unroll
                    for (int nf = 0; nf < 5; nf++)
                        mma_s8(acc[mf][nf], af[mf], bf[nf][2 * ks], bf[nf][2 * ks + 1]);
            }
            __syncthreads();
        }

        // epilogue (mma half)
#pragma unroll
        for (int mf = 0; mf < 4; mf++) {
            int r0 = bm + wm + mf * 16 + (lane >> 2);
            float f0 = frow[r0];
            float f1 = frow[r0 + 8];
#pragma unroll
            for (int nf = 0; nf < 5; nf++) {
                int c0 = bn + wn + nf * 8 + ((lane & 3) << 1);
                float2 v0, v1;
                v0.x = (float)acc[mf][nf][0] * f0;
                v0.y = (float)acc[mf][nf][1] * f0;
                v1.x = (float)acc[mf][nf][2] * f1;
                v1.y = (float)acc[mf][nf][3] * f1;
                *reinterpret_cast<float2*>(C + (size_t)r0 * N + c0)       = v0;
                *reinterpret_cast<float2*>(C + (size_t)(r0 + 8) * N + c0) = v1;
            }
        }
    } else {
        // ================= DP4A half: cols [160,256), warp tile 64x24 ==========
        int widd = warp - 8;
        int wm_d = (widd >> 2) * 64;     // row block: 64 rows
        int wn_d = (widd & 3) * 24;      // col block: 24 cols
        int rb = wm_d + (lane >> 2);     // thread rows: rb + 8*i (i<8)
        int cb = wn_d + (lane & 3);      // thread cols: cb + 4*j (j<6)

        int accd[8][6];
#pragma unroll
        for (int i = 0; i < 8; i++)
#pragma unroll
            for (int j = 0; j < 6; j++) accd[i][j] = 0;

        for (int s = 0; s < nst; s++) {
            asm volatile("cp.async.wait_group %0;" :: "n"(NSTAGE - 2) : "memory");
            __syncthreads();
            if (s + NSTAGE - 1 < nst) load_stage(s + NSTAGE - 1);
            asm volatile("cp.async.commit_group;" ::: "memory");

            uint32_t tb  = sbase + (uint32_t)(s & (NSTAGE - 1)) * STAGE_BYTES;
            uint32_t tbD = tb + REG_BD_OFF;

#pragma unroll
            for (int kb = 0; kb < 4; kb++) {
                int av[8][4];
#pragma unroll
                for (int i = 0; i < 8; i++)
                    lds128(av[i], tb + swz((uint32_t)(rb + 8 * i), (uint32_t)kb));
#pragma unroll
                for (int j = 0; j < 6; j++) {
                    int bv[4];
                    lds128(bv, tbD + swz((uint32_t)(cb + 4 * j), (uint32_t)kb));
#pragma unroll
                    for (int i = 0; i < 8; i++) {
                        accd[i][j] = __dp4a(av[i][0], bv[0], accd[i][j]);
                        accd[i][j] = __dp4a(av[i][1], bv[1], accd[i][j]);
                        accd[i][j] = __dp4a(av[i][2], bv[2], accd[i][j]);
                        accd[i][j] = __dp4a(av[i][3], bv[3], accd[i][j]);
                    }
                }
            }
            __syncthreads();
        }

        // epilogue (dp4a half)
#pragma unroll
        for (int i = 0; i < 8; i++) {
            int r = bm + rb + 8 * i;
            float f = frow[r];
            float* crow = C + (size_t)r * N + bn + BNT + cb;
#pragma unroll
            for (int j = 0; j < 6; j++)
                crow[4 * j] = (float)accd[i][j] * f;
        }
    }
}

// ---------------- host entry ----------------------------------------------------
extern "C" void kernel_launch(void* const* d_in, const int* in_sizes, int n_in,
                              void* d_out, int out_size) {
    const float* x  = (const float*)d_in[0];
    const float* w1 = (const float*)d_in[1];
    const float* g1 = (const float*)d_in[2];
    const float* w2 = (const float*)d_in[3];
    const float* g2 = (const float*)d_in[4];
    const float* w3 = (const float*)d_in[5];
    const float* g3 = (const float*)d_in[6];
    float* out = (float*)d_out;

    static bool attr_set = false;
    if (!attr_set) {
        cudaFuncSetAttribute(k_gemm_hy, cudaFuncAttributeMaxDynamicSharedMemorySize, GEMM_SMEM);
        attr_set = true;
    }

    // 0) weight abs-mean partials
    k_reduce_abs_all<<<dim3(1024, 3), 256>>>((const float4*)w1, (const float4*)w2,
                                             (const float4*)w3);
    // 1) finalize sums
    k_finalize<<<1, 256>>>();

    // 2) prep: ternarize weights + rmsnorm/act_quant of x
    k_prep<<<QW_BLOCKS + TOK, 256>>>((const float4*)w1, (const float4*)w2,
                                     (const float4*)w3, x, g1, g2);

    // 3) y1 and y2 fused (layer = blockIdx.z); lands at profile index 3
    k_gemm_hy<<<dim3(HH / BN, TOK / BM, 2), 512, GEMM_SMEM>>>(0, nullptr, HH, DD);

    // 4) h = silu(y1)*y2 -> rmsnorm(g3) -> int8
    k_combine<<<TOK, 256>>>(g3);

    // 5) out  (M=8192, N=2048, K=8192)
    k_gemm_hy<<<dim3(DD / BN, TOK / BM, 1), 512, GEMM_SMEM>>>(2, out, DD, HH);
}